// round 3
// baseline (speedup 1.0000x reference)
#include <cuda_runtime.h>

// YOLO post-process: (16, 25200, 85) fp32 -> (16, 25200, 6) fp32
//   row = [x, y, w, h, conf, cls0..cls79]
//   out = [x-w/2, y-h/2, x+w/2, y+h/2, conf*max(cls), argmax(cls)]  if conf*max(cls) > 0.25 else zeros
//
// Strategy: one warp per row. Lane-strided coalesced loads (85 = 32+32+21),
// warp-shuffle max/argmax over the 80 class scores, lanes 0..5 write the
// 6 output floats. Pure streaming, HBM-bound.

#define N_ROWS   (16 * 25200)   // 403200
#define N_CH     85
#define N_OUT    6
#define CONF_TH  0.25f
#define WARPS_PER_BLOCK 8
#define BLOCK_THREADS   (WARPS_PER_BLOCK * 32)

__global__ __launch_bounds__(BLOCK_THREADS)
void yolo_post_kernel(const float* __restrict__ in, float* __restrict__ out)
{
    const unsigned FULL = 0xFFFFFFFFu;
    int warp_global = (blockIdx.x * WARPS_PER_BLOCK) + (threadIdx.x >> 5);
    int lane = threadIdx.x & 31;
    if (warp_global >= N_ROWS) return;

    const float* row = in + (long long)warp_global * N_CH;

    // Coalesced lane-strided loads: elements [lane], [lane+32], [lane+64]
    float v0 = row[lane];
    float v1 = row[lane + 32];
    float v2 = (lane < N_CH - 64) ? row[lane + 64] : -1e30f;  // lanes 0..20 valid

    // --- class max/argmax over elements 5..84 (class idx 0..79) ---
    // v0 covers class idx lane-5 (lane>=5), v1 covers lane+27, v2 covers lane+59.
    float best;
    int   bidx;
    if (lane >= 5) { best = v0; bidx = lane - 5; }
    else           { best = -1e30f; bidx = 0x7FFFFFFF; }
    // v1's class index (lane+27) is always larger than v0's (lane-5): on tie keep v0.
    if (v1 > best) { best = v1; bidx = lane + 27; }
    if (lane < 21 && v2 > best) { best = v2; bidx = lane + 59; }

    // Warp reduction, first-index tie-break (matches jnp.argmax)
    #pragma unroll
    for (int off = 16; off > 0; off >>= 1) {
        float ov = __shfl_xor_sync(FULL, best, off);
        int   oi = __shfl_xor_sync(FULL, bidx, off);
        if (ov > best || (ov == best && oi < bidx)) { best = ov; bidx = oi; }
    }

    // Broadcast box params (held in v0 of lanes 0..4)
    float x    = __shfl_sync(FULL, v0, 0);
    float y    = __shfl_sync(FULL, v0, 1);
    float w    = __shfl_sync(FULL, v0, 2);
    float h    = __shfl_sync(FULL, v0, 3);
    float conf = __shfl_sync(FULL, v0, 4);

    float score = conf * best;
    bool  pass  = score > CONF_TH;

    float hw = 0.5f * w;
    float hh = 0.5f * h;

    float o = 0.0f;
    if (pass) {
        switch (lane) {
            case 0: o = x - hw;          break;
            case 1: o = y - hh;          break;
            case 2: o = x + hw;          break;
            case 3: o = y + hh;          break;
            case 4: o = score;           break;
            case 5: o = (float)bidx;     break;
            default: break;
        }
    }
    if (lane < N_OUT) {
        out[(long long)warp_global * N_OUT + lane] = o;
    }
}

extern "C" void kernel_launch(void* const* d_in, const int* in_sizes, int n_in,
                              void* d_out, int out_size)
{
    const float* in  = (const float*)d_in[0];
    float*       out = (float*)d_out;
    int n_warps  = N_ROWS;
    int n_blocks = (n_warps + WARPS_PER_BLOCK - 1) / WARPS_PER_BLOCK;  // 50400
    yolo_post_kernel<<<n_blocks, BLOCK_THREADS>>>(in, out);
}

// round 4
// speedup vs baseline: 2.2115x; 2.2115x over previous
#include <cuda_runtime.h>

// YOLO post-process: (16, 25200, 85) fp32 -> (16, 25200, 6) fp32
//   row = [x, y, w, h, conf, cls0..cls79]
//   out = [x-w/2, y-h/2, x+w/2, y+h/2, conf*max(cls), argmax(cls)]  if score > 0.25 else 0
//
// R3 strategy: block = 128 threads = 128 rows.
//   Stage 1: coalesced float4 gmem -> smem (block chunk is 16B-aligned: 128*85 % 4 == 0)
//   Stage 2: thread-per-row from smem. Stride-85 (odd) scalar LDS = bank-conflict-free.
//            Argmax via 4 independent accumulators (quarters) to break the serial chain;
//            ordered merge preserves first-index tie-break for free.
//   Stage 3: outputs staged in smem, coalesced float4 stores.

#define N_ROWS          (16 * 25200)     // 403200 = 3150 * 128
#define N_CH            85
#define N_OUT           6
#define CONF_TH         0.25f
#define ROWS_PER_BLOCK  128
#define BLOCK_THREADS   128
#define FLOATS_PER_BLK  (ROWS_PER_BLOCK * N_CH)        // 10880
#define VEC4_PER_BLK    (FLOATS_PER_BLK / 4)           // 2720
#define OUT_VEC4_PER_BLK (ROWS_PER_BLOCK * N_OUT / 4)  // 192

__global__ __launch_bounds__(BLOCK_THREADS)
void yolo_post_kernel(const float4* __restrict__ in4, float4* __restrict__ out4)
{
    __shared__ float smem[FLOATS_PER_BLK];

    const int tid = threadIdx.x;
    const int blk = blockIdx.x;

    // ---- Stage 1: coalesced vector load gmem -> smem ----
    {
        const float4* src = in4 + (size_t)blk * VEC4_PER_BLK;
        float4* dst = reinterpret_cast<float4*>(smem);
        #pragma unroll 4
        for (int i = tid; i < VEC4_PER_BLK; i += BLOCK_THREADS) {
            dst[i] = src[i];
        }
    }
    __syncthreads();

    // ---- Stage 2: thread-per-row compute ----
    const float* row = smem + tid * N_CH;

    const float x    = row[0];
    const float y    = row[1];
    const float w    = row[2];
    const float h    = row[3];
    const float conf = row[4];

    // 4 independent accumulators over class quarters [0,20) [20,40) [40,60) [60,80)
    float b0 = row[5 +  0], b1 = row[5 + 20], b2 = row[5 + 40], b3 = row[5 + 60];
    int   i0 = 0,           i1 = 20,          i2 = 40,          i3 = 60;

    #pragma unroll
    for (int c = 1; c < 20; c++) {
        float v0 = row[5 +  0 + c];
        float v1 = row[5 + 20 + c];
        float v2 = row[5 + 40 + c];
        float v3 = row[5 + 60 + c];
        if (v0 > b0) { b0 = v0; i0 =  0 + c; }
        if (v1 > b1) { b1 = v1; i1 = 20 + c; }
        if (v2 > b2) { b2 = v2; i2 = 40 + c; }
        if (v3 > b3) { b3 = v3; i3 = 60 + c; }
    }
    // Ordered merge: on ties keep the earlier quarter (lower index) -> first-index semantics
    if (b1 > b0) { b0 = b1; i0 = i1; }
    if (b2 > b0) { b0 = b2; i0 = i2; }
    if (b3 > b0) { b0 = b3; i0 = i3; }

    const float score = conf * b0;
    const bool  pass  = score > CONF_TH;

    const float hw = 0.5f * w;
    const float hh = 0.5f * h;

    float o0 = 0.f, o1 = 0.f, o2 = 0.f, o3 = 0.f, o4 = 0.f, o5 = 0.f;
    if (pass) {
        o0 = x - hw;
        o1 = y - hh;
        o2 = x + hw;
        o3 = y + hh;
        o4 = score;
        o5 = (float)i0;
    }

    // ---- Stage 3: stage outputs in smem, coalesced store ----
    __syncthreads();   // all reads of row data done before overwrite
    float* so = smem + tid * N_OUT;
    so[0] = o0; so[1] = o1; so[2] = o2; so[3] = o3; so[4] = o4; so[5] = o5;
    __syncthreads();

    {
        const float4* src = reinterpret_cast<const float4*>(smem);
        float4* dst = out4 + (size_t)blk * OUT_VEC4_PER_BLK;
        #pragma unroll
        for (int i = tid; i < OUT_VEC4_PER_BLK; i += BLOCK_THREADS) {
            dst[i] = src[i];
        }
    }
}

extern "C" void kernel_launch(void* const* d_in, const int* in_sizes, int n_in,
                              void* d_out, int out_size)
{
    const float4* in4  = (const float4*)d_in[0];
    float4*       out4 = (float4*)d_out;
    int n_blocks = N_ROWS / ROWS_PER_BLOCK;   // 3150
    yolo_post_kernel<<<n_blocks, BLOCK_THREADS>>>(in4, out4);
}

// round 5
// speedup vs baseline: 3.0175x; 1.3645x over previous
#include <cuda_runtime.h>
#include <cstdint>

// YOLO post-process: (16, 25200, 85) fp32 -> (16, 25200, 6) fp32
//
// R4: persistent blocks, double-buffered cp.async.bulk (DMA) pipeline.
//   - 2 input buffers (43520 B each) + 2 output staging buffers (3072 B) per block
//   - one thread issues a bulk copy for tile t+1 while all threads compute tile t
//   - compute: thread-per-row out of smem (stride-85 scalar LDS = conflict-free),
//     4-way unrolled argmax with ordered merge (first-index tie-break)
//   - output staged in smem, coalesced float4 stores

#define N_ROWS        403200          // 16 * 25200
#define N_CH          85
#define N_OUT         6
#define CONF_TH       0.25f
#define TILE_ROWS     128
#define NT            (N_ROWS / TILE_ROWS)   // 3150
#define BLOCK_THREADS 128
#define TILE_FLOATS   (TILE_ROWS * N_CH)     // 10880
#define TILE_BYTES    (TILE_FLOATS * 4)      // 43520
#define OUT_FLOATS    (TILE_ROWS * N_OUT)    // 768
#define OUT_VEC4      (OUT_FLOATS / 4)       // 192
#define GRID_BLOCKS   296                    // 2 per SM * 148

// smem byte layout (dynamic):
//   [0,8)      mbar0
//   [8,16)     mbar1
//   [32, +T)   in_buf0
//   [.., +T)   in_buf1
//   [.., +3072) out_buf0
//   [.., +3072) out_buf1
#define SM_IN0   32
#define SM_IN1   (SM_IN0 + TILE_BYTES)
#define SM_OUT0  (SM_IN1 + TILE_BYTES)
#define SM_OUT1  (SM_OUT0 + OUT_FLOATS * 4)
#define SM_TOTAL (SM_OUT1 + OUT_FLOATS * 4)  // 93216

__device__ __forceinline__ unsigned smem_u32(const void* p) {
    unsigned a;
    asm("{ .reg .u64 t; cvta.to.shared.u64 t, %1; cvt.u32.u64 %0, t; }"
        : "=r"(a) : "l"(p));
    return a;
}

__device__ __forceinline__ void mbar_init(unsigned addr, unsigned count) {
    asm volatile("mbarrier.init.shared.b64 [%0], %1;" :: "r"(addr), "r"(count) : "memory");
}

__device__ __forceinline__ void bulk_load(unsigned dst_smem, const void* gsrc,
                                          unsigned bytes, unsigned mbar) {
    asm volatile("mbarrier.arrive.expect_tx.shared.b64 _, [%0], %1;"
                 :: "r"(mbar), "r"(bytes) : "memory");
    asm volatile("cp.async.bulk.shared::cta.global.mbarrier::complete_tx::bytes "
                 "[%0], [%1], %2, [%3];"
                 :: "r"(dst_smem), "l"(gsrc), "r"(bytes), "r"(mbar) : "memory");
}

__device__ __forceinline__ void mbar_wait(unsigned addr, unsigned parity) {
    asm volatile(
        "{\n\t"
        ".reg .pred P;\n\t"
        "W%=:\n\t"
        "mbarrier.try_wait.parity.acquire.cta.shared::cta.b64 P, [%0], %1, 0x989680;\n\t"
        "@P bra D%=;\n\t"
        "bra W%=;\n\t"
        "D%=:\n\t"
        "}"
        :: "r"(addr), "r"(parity) : "memory");
}

__global__ __launch_bounds__(BLOCK_THREADS, 2)
void yolo_post_kernel(const float* __restrict__ in, float4* __restrict__ out4)
{
    extern __shared__ char sb[];
    const unsigned base = smem_u32(sb);
    const unsigned mbar0 = base + 0;
    const unsigned mbar1 = base + 8;
    float* const in_buf0  = reinterpret_cast<float*>(sb + SM_IN0);
    float* const in_buf1  = reinterpret_cast<float*>(sb + SM_IN1);
    float* const out_buf0 = reinterpret_cast<float*>(sb + SM_OUT0);
    float* const out_buf1 = reinterpret_cast<float*>(sb + SM_OUT1);

    const int tid = threadIdx.x;

    if (tid == 0) {
        mbar_init(mbar0, 1);
        mbar_init(mbar1, 1);
    }
    __syncthreads();

    // Prologue: issue DMA for this block's first tile into buffer 0.
    if (tid == 0) {
        const float* g = in + (size_t)blockIdx.x * TILE_FLOATS;
        bulk_load(base + SM_IN0, g, TILE_BYTES, mbar0);
    }

    int it = 0;
    for (int tile = blockIdx.x; tile < NT; tile += GRID_BLOCKS, ++it) {
        const int buf = it & 1;

        // Issue DMA for the next tile into the other buffer (its previous
        // contents were consumed at iteration it-1, fenced by that iteration's
        // __syncthreads which tid 0 has passed).
        const int next_tile = tile + GRID_BLOCKS;
        if (tid == 0 && next_tile < NT) {
            const unsigned nb_smem = (buf ? base + SM_IN0 : base + SM_IN1);
            const unsigned nb_mbar = (buf ? mbar0 : mbar1);
            const float* g = in + (size_t)next_tile * TILE_FLOATS;
            bulk_load(nb_smem, g, TILE_BYTES, nb_mbar);
        }

        // Wait for the current tile's DMA.
        mbar_wait(buf ? mbar1 : mbar0, (unsigned)((it >> 1) & 1));

        // ---- compute: thread-per-row ----
        const float* row = (buf ? in_buf1 : in_buf0) + tid * N_CH;

        const float x    = row[0];
        const float y    = row[1];
        const float w    = row[2];
        const float h    = row[3];
        const float conf = row[4];

        float b0 = row[5 +  0], b1 = row[5 + 20], b2 = row[5 + 40], b3 = row[5 + 60];
        int   i0 = 0,           i1 = 20,          i2 = 40,          i3 = 60;

        #pragma unroll
        for (int c = 1; c < 20; c++) {
            float v0 = row[5 +  0 + c];
            float v1 = row[5 + 20 + c];
            float v2 = row[5 + 40 + c];
            float v3 = row[5 + 60 + c];
            if (v0 > b0) { b0 = v0; i0 =  0 + c; }
            if (v1 > b1) { b1 = v1; i1 = 20 + c; }
            if (v2 > b2) { b2 = v2; i2 = 40 + c; }
            if (v3 > b3) { b3 = v3; i3 = 60 + c; }
        }
        // Ordered merge: ties keep the earlier quarter -> first-index semantics.
        if (b1 > b0) { b0 = b1; i0 = i1; }
        if (b2 > b0) { b0 = b2; i0 = i2; }
        if (b3 > b0) { b0 = b3; i0 = i3; }

        const float score = conf * b0;
        const bool  pass  = score > CONF_TH;
        const float hw = 0.5f * w;
        const float hh = 0.5f * h;

        float o0 = 0.f, o1 = 0.f, o2 = 0.f, o3 = 0.f, o4 = 0.f, o5 = 0.f;
        if (pass) {
            o0 = x - hw;
            o1 = y - hh;
            o2 = x + hw;
            o3 = y + hh;
            o4 = score;
            o5 = (float)i0;
        }

        // ---- stage outputs, coalesced store ----
        float* so = (buf ? out_buf1 : out_buf0) + tid * N_OUT;
        so[0] = o0; so[1] = o1; so[2] = o2; so[3] = o3; so[4] = o4; so[5] = o5;
        __syncthreads();

        {
            const float4* src = reinterpret_cast<const float4*>(buf ? out_buf1 : out_buf0);
            float4* dst = out4 + (size_t)tile * OUT_VEC4;
            #pragma unroll
            for (int i = tid; i < OUT_VEC4; i += BLOCK_THREADS)
                dst[i] = src[i];
        }
    }
}

extern "C" void kernel_launch(void* const* d_in, const int* in_sizes, int n_in,
                              void* d_out, int out_size)
{
    const float* in  = (const float*)d_in[0];
    float4*      out = (float4*)d_out;
    cudaFuncSetAttribute(yolo_post_kernel,
                         cudaFuncAttributeMaxDynamicSharedMemorySize, SM_TOTAL);
    yolo_post_kernel<<<GRID_BLOCKS, BLOCK_THREADS, SM_TOTAL>>>(in, out);
}